// round 1
// baseline (speedup 1.0000x reference)
#include <cuda_runtime.h>
#include <cstdint>

// ---------------------------------------------------------------------------
// DynamicProjectionModule: Q/K/V projections + routed redundancy projections.
//
// Shapes (all fp32):
//   img_tokens [8,1024,1024]  txt_tokens [8,1024,768]
//   Wq [1024,1024] Wk/Wv [1024,768]
//   Wq_banks [3,1024,1024] Wk_banks [3,1024,768]
//   Wrq [3,1024] Wrk [3,768]
// Output: concat(Q, K, V, Q', K'), each [8,16,1024,64] fp32.
//
// STE forward value == hard one-hot, so Q'/K' use only the argmax bank per
// token. We route (fp64 accumulation for argmax robustness), compact tokens
// into per-(side,bank) lists, then run grouped GEMMs that gather rows.
// ---------------------------------------------------------------------------

#define BSZ      8
#define SEQ      1024
#define IMG_DIM  1024
#define TXT_DIM  768
#define INNER    1024
#define NHEADS   16
#define HD       64
#define MROWS    (BSZ * SEQ)                         /* 8192 */
#define TELEMS   ((long long)BSZ * NHEADS * SEQ * HD) /* 8388608 */

// Device scratch (no allocations allowed).
__device__ int g_cnt[6];            // slots: 0..2 img banks, 3..5 txt banks
__device__ int g_list[6][MROWS];

__global__ void init_kernel() {
    if (threadIdx.x < 6) g_cnt[threadIdx.x] = 0;
}

// One warp per token; fp64 accumulation so argmax matches jax's fp32 scores
// except in measure-zero tie cases.
__global__ void route_kernel(const float* __restrict__ img,
                             const float* __restrict__ txt,
                             const float* __restrict__ Wrq,
                             const float* __restrict__ Wrk) {
    int warp = (blockIdx.x * blockDim.x + threadIdx.x) >> 5;
    int lane = threadIdx.x & 31;
    int side = blockIdx.y;           // 0 = img/q, 1 = txt/k
    if (warp >= MROWS) return;

    const float* x;
    const float* wr;
    int dim;
    if (side == 0) { x = img + (size_t)warp * IMG_DIM; wr = Wrq; dim = IMG_DIM; }
    else           { x = txt + (size_t)warp * TXT_DIM; wr = Wrk; dim = TXT_DIM; }

    double s0 = 0.0, s1 = 0.0, s2 = 0.0;
    for (int k = lane; k < dim; k += 32) {
        double xv = (double)x[k];
        s0 += xv * (double)wr[k];
        s1 += xv * (double)wr[dim + k];
        s2 += xv * (double)wr[2 * dim + k];
    }
    #pragma unroll
    for (int off = 16; off; off >>= 1) {
        s0 += __shfl_down_sync(0xffffffffu, s0, off);
        s1 += __shfl_down_sync(0xffffffffu, s1, off);
        s2 += __shfl_down_sync(0xffffffffu, s2, off);
    }
    if (lane == 0) {
        int p = 0; double best = s0;
        if (s1 > best) { best = s1; p = 1; }   // strict > keeps first index on ties (jax argmax)
        if (s2 > best) { best = s2; p = 2; }
        int slot = side * 3 + p;
        int pos = atomicAdd(&g_cnt[slot], 1);
        g_list[slot][pos] = warp;
    }
}

// Classic 128x128x8 fp32 SGEMM: C[m,n] = dot(X[m,:], W[n,:]), with optional
// row gathering through g_list[slot] (slot<0 => identity rows). Output is
// scattered into head layout: (b, h, s, d) with m=b*1024+s, n=h*64+d.
__global__ void __launch_bounds__(256, 2)
gemm_kernel(const float* __restrict__ X, const float* __restrict__ W,
            float* __restrict__ out, int Kdim, int slot, long long outBase) {
    __shared__ float As[8][128];
    __shared__ float Bs[8][128];
    __shared__ int   rowmap[128];

    const int rowBase = blockIdx.x * 128;
    const int colBase = blockIdx.y * 128;
    const int cnt = (slot >= 0) ? g_cnt[slot] : MROWS;
    if (rowBase >= cnt) return;      // whole block beyond this route's token count

    const int tid = threadIdx.x;
    if (tid < 128) {
        int gr = rowBase + tid;
        rowmap[tid] = (slot < 0) ? gr : ((gr < cnt) ? g_list[slot][gr] : 0);
    }
    __syncthreads();

    // Per-thread tile-load coordinates: 256 threads x float4 = 1024 floats/tile.
    const int la    = tid * 4;
    const int laRow = la >> 3;       // 0..127  (A: token row; B: output col n)
    const int laK   = la & 7;        // 0 or 4
    const float* aPtr = X + (size_t)rowmap[laRow] * Kdim + laK;
    const float* bPtr = W + (size_t)(colBase + laRow) * Kdim + laK;

    const int rowg = (tid >> 4) * 8; // this thread's 8-row group
    const int colg = (tid & 15) * 8; // this thread's 8-col group

    float acc[8][8];
    #pragma unroll
    for (int i = 0; i < 8; i++)
        #pragma unroll
        for (int j = 0; j < 8; j++) acc[i][j] = 0.f;

    for (int k0 = 0; k0 < Kdim; k0 += 8) {
        float4 av = *reinterpret_cast<const float4*>(aPtr + k0);
        float4 bv = *reinterpret_cast<const float4*>(bPtr + k0);
        As[laK + 0][laRow] = av.x; As[laK + 1][laRow] = av.y;
        As[laK + 2][laRow] = av.z; As[laK + 3][laRow] = av.w;
        Bs[laK + 0][laRow] = bv.x; Bs[laK + 1][laRow] = bv.y;
        Bs[laK + 2][laRow] = bv.z; Bs[laK + 3][laRow] = bv.w;
        __syncthreads();

        #pragma unroll
        for (int kk = 0; kk < 8; kk++) {
            float ar[8], br[8];
            float4 a0 = *reinterpret_cast<const float4*>(&As[kk][rowg]);
            float4 a1 = *reinterpret_cast<const float4*>(&As[kk][rowg + 4]);
            float4 b0 = *reinterpret_cast<const float4*>(&Bs[kk][colg]);
            float4 b1 = *reinterpret_cast<const float4*>(&Bs[kk][colg + 4]);
            ar[0]=a0.x; ar[1]=a0.y; ar[2]=a0.z; ar[3]=a0.w;
            ar[4]=a1.x; ar[5]=a1.y; ar[6]=a1.z; ar[7]=a1.w;
            br[0]=b0.x; br[1]=b0.y; br[2]=b0.z; br[3]=b0.w;
            br[4]=b1.x; br[5]=b1.y; br[6]=b1.z; br[7]=b1.w;
            #pragma unroll
            for (int i = 0; i < 8; i++)
                #pragma unroll
                for (int j = 0; j < 8; j++)
                    acc[i][j] += ar[i] * br[j];
        }
        __syncthreads();
    }

    // Scatter to head layout. The 8 cols of a thread stay inside one head
    // (colg % 8 == 0, 8 | 64), so two float4 stores per row.
    const int n0 = colBase + colg;
    const int h  = n0 >> 6;
    const int d0 = n0 & 63;
    #pragma unroll
    for (int i = 0; i < 8; i++) {
        int gr = rowBase + rowg + i;
        if (gr >= cnt) continue;
        int m = rowmap[rowg + i];
        int b = m >> 10;
        int s = m & 1023;
        long long off = outBase
                      + (((long long)(b * NHEADS + h) * SEQ + s) * HD) + d0;
        float4 v0 = make_float4(acc[i][0], acc[i][1], acc[i][2], acc[i][3]);
        float4 v1 = make_float4(acc[i][4], acc[i][5], acc[i][6], acc[i][7]);
        *reinterpret_cast<float4*>(out + off)     = v0;
        *reinterpret_cast<float4*>(out + off + 4) = v1;
    }
}

extern "C" void kernel_launch(void* const* d_in, const int* in_sizes, int n_in,
                              void* d_out, int out_size) {
    (void)in_sizes; (void)n_in; (void)out_size;
    const float* img = (const float*)d_in[0];
    const float* txt = (const float*)d_in[1];
    const float* Wq  = (const float*)d_in[2];
    const float* Wk  = (const float*)d_in[3];
    const float* Wv  = (const float*)d_in[4];
    const float* Wqb = (const float*)d_in[5];
    const float* Wkb = (const float*)d_in[6];
    const float* Wrq = (const float*)d_in[7];
    const float* Wrk = (const float*)d_in[8];
    float* out = (float*)d_out;

    init_kernel<<<1, 32>>>();
    route_kernel<<<dim3(1024, 2), 256>>>(img, txt, Wrq, Wrk);

    dim3 grid(MROWS / 128, INNER / 128);  // 64 x 8
    dim3 blk(256);

    // Plain projections.
    gemm_kernel<<<grid, blk>>>(img, Wq, out, IMG_DIM, -1, 0LL);
    gemm_kernel<<<grid, blk>>>(txt, Wk, out, TXT_DIM, -1, TELEMS);
    gemm_kernel<<<grid, blk>>>(txt, Wv, out, TXT_DIM, -1, 2 * TELEMS);

    // Grouped (routed) projections: one launch per bank; blocks beyond the
    // route's token count exit immediately.
    for (int p = 0; p < 3; p++)
        gemm_kernel<<<grid, blk>>>(img, Wqb + (size_t)p * INNER * IMG_DIM,
                                   out, IMG_DIM, p, 3 * TELEMS);
    for (int p = 0; p < 3; p++)
        gemm_kernel<<<grid, blk>>>(txt, Wkb + (size_t)p * INNER * TXT_DIM,
                                   out, TXT_DIM, 3 + p, 4 * TELEMS);
}

// round 3
// speedup vs baseline: 2.4693x; 2.4693x over previous
#include <cuda_runtime.h>
#include <cuda_bf16.h>
#include <cstdint>

// ---------------------------------------------------------------------------
// DynamicProjectionModule via warp-level bf16 tensor-core MMA (arch-portable:
// mma.sync m16n8k16 + ldmatrix + cp.async only — NO tcgen05, which fails on
// the harness's plain compute_103 PTX pass).
//
// fp32 accuracy via bf16 hi/lo 3-split as one GEMM with K' = 3K:
//   A' = [Ahi|Alo|Ahi],  B' = [Bhi|Bhi|Blo]  =>  err ~1.5e-5 rel.
// Routed projections (STE forward == argmax one-hot) as grouped GEMMs over
// per-bank compacted token lists.
// ---------------------------------------------------------------------------

#define BSZ      8
#define SEQ      1024
#define IMG_DIM  1024
#define TXT_DIM  768
#define INNER    1024
#define MROWS    (BSZ * SEQ)
#define TELEMS   ((long long)MROWS * INNER)

#define K3_IMG   (3 * IMG_DIM)   /* 3072 */
#define K3_TXT   (3 * TXT_DIM)   /* 2304 */

// ---- device scratch --------------------------------------------------------
__device__ int g_cnt[6];
__device__ int g_list[6][MROWS];

__device__ __nv_bfloat16 c_img[MROWS * K3_IMG];
__device__ __nv_bfloat16 c_txt[MROWS * K3_TXT];
__device__ __nv_bfloat16 c_wq [INNER * K3_IMG];
__device__ __nv_bfloat16 c_wk [INNER * K3_TXT];
__device__ __nv_bfloat16 c_wv [INNER * K3_TXT];
__device__ __nv_bfloat16 c_wqb[3 * INNER * K3_IMG];
__device__ __nv_bfloat16 c_wkb[3 * INNER * K3_TXT];

// ---- helpers ---------------------------------------------------------------
__device__ __forceinline__ uint32_t smem_u32(const void* p) {
    uint32_t a;
    asm("{ .reg .u64 t; cvta.to.shared.u64 t, %1; cvt.u32.u64 %0, t; }" : "=r"(a) : "l"(p));
    return a;
}
__device__ __forceinline__ void cp16(uint32_t d, const void* g) {
    asm volatile("cp.async.cg.shared.global [%0], [%1], 16;" :: "r"(d), "l"(g));
}
__device__ __forceinline__ void cp_commit() { asm volatile("cp.async.commit_group;" ::: "memory"); }
template<int N> __device__ __forceinline__ void cp_wait() {
    asm volatile("cp.async.wait_group %0;" :: "n"(N) : "memory");
}
__device__ __forceinline__ void ldsm_x4(uint32_t& r0, uint32_t& r1, uint32_t& r2, uint32_t& r3,
                                        uint32_t addr) {
    asm volatile("ldmatrix.sync.aligned.m8n8.x4.shared.b16 {%0,%1,%2,%3}, [%4];"
                 : "=r"(r0), "=r"(r1), "=r"(r2), "=r"(r3) : "r"(addr));
}
__device__ __forceinline__ void mma16816(float* c, const uint32_t* a, const uint32_t* b) {
    asm volatile("mma.sync.aligned.m16n8k16.row.col.f32.bf16.bf16.f32 "
                 "{%0,%1,%2,%3}, {%4,%5,%6,%7}, {%8,%9}, {%0,%1,%2,%3};"
                 : "+f"(c[0]), "+f"(c[1]), "+f"(c[2]), "+f"(c[3])
                 : "r"(a[0]), "r"(a[1]), "r"(a[2]), "r"(a[3]), "r"(b[0]), "r"(b[1]));
}
#define SWZ(x) ((x) ^ (((x) >> 3) & 0x70))

// ---- setup -----------------------------------------------------------------
__global__ void init_kernel() {
    if (threadIdx.x < 6) g_cnt[threadIdx.x] = 0;
}

// fp64 accumulation: argmax must match jax fp32 scores (one flipped route
// corrupts an entire 1024-wide row).
__global__ void route_kernel(const float* __restrict__ img, const float* __restrict__ txt,
                             const float* __restrict__ Wrq, const float* __restrict__ Wrk) {
    int warp = (blockIdx.x * blockDim.x + threadIdx.x) >> 5;
    int lane = threadIdx.x & 31;
    int side = blockIdx.y;
    if (warp >= MROWS) return;
    const float* x;  const float* wr;  int dim;
    if (side == 0) { x = img + (size_t)warp * IMG_DIM; wr = Wrq; dim = IMG_DIM; }
    else           { x = txt + (size_t)warp * TXT_DIM; wr = Wrk; dim = TXT_DIM; }
    double s0 = 0, s1 = 0, s2 = 0;
    for (int k = lane; k < dim; k += 32) {
        double xv = (double)x[k];
        s0 += xv * (double)wr[k];
        s1 += xv * (double)wr[dim + k];
        s2 += xv * (double)wr[2 * dim + k];
    }
    #pragma unroll
    for (int off = 16; off; off >>= 1) {
        s0 += __shfl_down_sync(0xffffffffu, s0, off);
        s1 += __shfl_down_sync(0xffffffffu, s1, off);
        s2 += __shfl_down_sync(0xffffffffu, s2, off);
    }
    if (lane == 0) {
        int p = 0; double best = s0;
        if (s1 > best) { best = s1; p = 1; }
        if (s2 > best) { best = s2; p = 2; }
        int pos = atomicAdd(&g_cnt[side * 3 + p], 1);
        g_list[side * 3 + p][pos] = warp;
    }
}

// fp32 -> bf16 hi/lo split, K' = 3K.  bside=0: [hi|lo|hi]; bside=1: [hi|hi|lo].
__global__ void convert_kernel(const float* __restrict__ X, __nv_bfloat16* __restrict__ Y,
                               int K, int total, int bside) {
    for (int i = blockIdx.x * blockDim.x + threadIdx.x; i < total;
         i += gridDim.x * blockDim.x) {
        int r = i / K, k = i - r * K;
        float x = X[i];
        __nv_bfloat16 hi = __float2bfloat16(x);
        __nv_bfloat16 lo = __float2bfloat16(x - __bfloat162float(hi));
        size_t base = (size_t)r * (3 * K) + k;
        if (bside) { Y[base] = hi; Y[base + K] = hi;  Y[base + 2 * K] = lo; }
        else       { Y[base] = hi; Y[base + K] = lo;  Y[base + 2 * K] = hi; }
    }
}

// ---- HMMA GEMM -------------------------------------------------------------
// CTA tile 128(M) x 128(N), K-chunk 64 (128B rows, SW128 swizzle), 3-stage
// cp.async pipeline. 8 warps in 4(M) x 2(N); warp tile 32 x 64.
// C[m,n] = dot(A'[rowmap[m],:], B'[colBase+n,:]). Output scattered to
// [B,16,1024,64] head layout.
#define KC        64
#define STAGES    3
#define AB_BYTES  (128 * 128)
#define STG_BYTES (2 * AB_BYTES)          /* 32 KB */
#define CTRL_OFF  (STAGES * STG_BYTES)    /* 96 KB */
#define SMEM_TOTAL (CTRL_OFF + 512)

__global__ void __launch_bounds__(256, 2)
hmma_gemm(const __nv_bfloat16* __restrict__ A, const __nv_bfloat16* __restrict__ B,
          float* __restrict__ out, int K3, int slot, long long outBase)
{
    extern __shared__ char smem[];
    const int tid  = threadIdx.x;
    const int wid  = tid >> 5;
    const int lane = tid & 31;
    const int rowBase = blockIdx.x * 128;
    const int colBase = blockIdx.y * 128;
    const int cnt = (slot >= 0) ? g_cnt[slot] : MROWS;
    if (rowBase >= cnt) return;

    const uint32_t sb = smem_u32(smem);
    int* s_rowmap = (int*)(smem + CTRL_OFF);
    if (tid < 128) {
        int gr = rowBase + tid;
        s_rowmap[tid] = (slot < 0) ? gr : ((gr < cnt) ? g_list[slot][gr] : 0);
    }
    __syncthreads();

    const int wm = (wid >> 1) * 32;   // warp M offset
    const int wn = (wid & 1) * 64;    // warp N offset

    // per-stage loads: 2048 x 16B; thread tid does 8 (j<4 -> A, j>=4 -> B)
    auto load_stage = [&](int buf, int chunk) {
        const int kc = chunk * KC;
        const uint32_t aB = sb + buf * STG_BYTES;
        #pragma unroll
        for (int j = 0; j < 8; j++) {
            int t = tid + j * 256;
            int r = t >> 3, c = t & 7;
            if (j < 4) {
                const __nv_bfloat16* g = A + (size_t)s_rowmap[r] * K3 + kc + c * 8;
                cp16(aB + SWZ(r * 128 + c * 16), g);
            } else {
                int rb = r - 128;
                const __nv_bfloat16* g = B + (size_t)(colBase + rb) * K3 + kc + c * 8;
                cp16(aB + AB_BYTES + SWZ(rb * 128 + c * 16), g);
            }
        }
    };

    float acc[2][8][4];
    #pragma unroll
    for (int m = 0; m < 2; m++)
        #pragma unroll
        for (int n = 0; n < 8; n++)
            #pragma unroll
            for (int q = 0; q < 4; q++) acc[m][n][q] = 0.f;

    const int NCHUNK = K3 / KC;

    load_stage(0, 0); cp_commit();
    load_stage(1, 1); cp_commit();

    for (int c = 0; c < NCHUNK; c++) {
        const int buf = c % STAGES;
        cp_wait<STAGES - 2>();
        __syncthreads();

        if (c + 2 < NCHUNK) load_stage((c + 2) % STAGES, c + 2);
        cp_commit();

        const uint32_t aB = sb + buf * STG_BYTES;
        const uint32_t bB = aB + AB_BYTES;

        #pragma unroll
        for (int ks = 0; ks < 4; ks++) {
            // A fragments: 2 m16k16 tiles
            uint32_t a[2][4];
            #pragma unroll
            for (int m = 0; m < 2; m++) {
                int row = wm + m * 16 + (lane & 15);
                int c16 = ks * 2 + (lane >> 4);
                ldsm_x4(a[m][0], a[m][1], a[m][2], a[m][3],
                        aB + SWZ(row * 128 + c16 * 16));
            }
            // B fragments: 4 n16k16 tiles -> 8 n8 frags
            uint32_t b[8][2];
            #pragma unroll
            for (int t = 0; t < 4; t++) {
                int nrow = wn + t * 16 + (lane & 7) + ((lane >> 4) << 3);
                int c16  = ks * 2 + ((lane >> 3) & 1);
                uint32_t r0, r1, r2, r3;
                ldsm_x4(r0, r1, r2, r3, bB + SWZ(nrow * 128 + c16 * 16));
                b[2 * t][0] = r0;  b[2 * t][1] = r1;
                b[2 * t + 1][0] = r2; b[2 * t + 1][1] = r3;
            }
            #pragma unroll
            for (int m = 0; m < 2; m++)
                #pragma unroll
                for (int n = 0; n < 8; n++)
                    mma16816(acc[m][n], a[m], b[n]);
        }
        __syncthreads();
    }

    // epilogue: rows = wm + m*16 + (lane>>2) + {0,8}; cols = wn + n*8 + 2*(lane&3)+{0,1}
    const int head = (colBase + wn) >> 6;
    #pragma unroll
    for (int m = 0; m < 2; m++) {
        #pragma unroll
        for (int half = 0; half < 2; half++) {
            int rr = wm + m * 16 + (lane >> 2) + half * 8;
            if (rowBase + rr >= cnt) continue;
            int mt = s_rowmap[rr];
            int bb = mt >> 10, sq = mt & 1023;
            long long off0 = outBase + (((long long)(bb * 16 + head) * 1024 + sq) * 64);
            #pragma unroll
            for (int n = 0; n < 8; n++) {
                int d = n * 8 + 2 * (lane & 3);
                float2 v = make_float2(acc[m][n][half * 2], acc[m][n][half * 2 + 1]);
                *reinterpret_cast<float2*>(out + off0 + d) = v;
            }
        }
    }
}

// ---- host ------------------------------------------------------------------
extern "C" void kernel_launch(void* const* d_in, const int* in_sizes, int n_in,
                              void* d_out, int out_size) {
    (void)in_sizes; (void)n_in; (void)out_size;
    const float* img = (const float*)d_in[0];
    const float* txt = (const float*)d_in[1];
    const float* Wq  = (const float*)d_in[2];
    const float* Wk  = (const float*)d_in[3];
    const float* Wv  = (const float*)d_in[4];
    const float* Wqb = (const float*)d_in[5];
    const float* Wkb = (const float*)d_in[6];
    const float* Wrq = (const float*)d_in[7];
    const float* Wrk = (const float*)d_in[8];
    float* out = (float*)d_out;

    cudaFuncSetAttribute(hmma_gemm, cudaFuncAttributeMaxDynamicSharedMemorySize,
                         SMEM_TOTAL);

    init_kernel<<<1, 32>>>();
    route_kernel<<<dim3(1024, 2), 256>>>(img, txt, Wrq, Wrk);

    __nv_bfloat16 *p_img, *p_txt, *p_wq, *p_wk, *p_wv, *p_wqb, *p_wkb;
    cudaGetSymbolAddress((void**)&p_img, c_img);
    cudaGetSymbolAddress((void**)&p_txt, c_txt);
    cudaGetSymbolAddress((void**)&p_wq,  c_wq);
    cudaGetSymbolAddress((void**)&p_wk,  c_wk);
    cudaGetSymbolAddress((void**)&p_wv,  c_wv);
    cudaGetSymbolAddress((void**)&p_wqb, c_wqb);
    cudaGetSymbolAddress((void**)&p_wkb, c_wkb);

    const int CB = 2368;
    convert_kernel<<<CB, 256>>>(img, p_img, IMG_DIM, MROWS * IMG_DIM, 0);
    convert_kernel<<<CB, 256>>>(txt, p_txt, TXT_DIM, MROWS * TXT_DIM, 0);
    convert_kernel<<<CB, 256>>>(Wq,  p_wq,  IMG_DIM, INNER * IMG_DIM, 1);
    convert_kernel<<<CB, 256>>>(Wk,  p_wk,  TXT_DIM, INNER * TXT_DIM, 1);
    convert_kernel<<<CB, 256>>>(Wv,  p_wv,  TXT_DIM, INNER * TXT_DIM, 1);
    convert_kernel<<<CB, 256>>>(Wqb, p_wqb, IMG_DIM, 3 * INNER * IMG_DIM, 1);
    convert_kernel<<<CB, 256>>>(Wkb, p_wkb, TXT_DIM, 3 * INNER * TXT_DIM, 1);

    dim3 grid(MROWS / 128, INNER / 128);   // 64 x 8
    dim3 blk(256);

    hmma_gemm<<<grid, blk, SMEM_TOTAL>>>(p_img, p_wq, out, K3_IMG, -1, 0LL);
    hmma_gemm<<<grid, blk, SMEM_TOTAL>>>(p_txt, p_wk, out, K3_TXT, -1, TELEMS);
    hmma_gemm<<<grid, blk, SMEM_TOTAL>>>(p_txt, p_wv, out, K3_TXT, -1, 2 * TELEMS);
    for (int p = 0; p < 3; p++)
        hmma_gemm<<<grid, blk, SMEM_TOTAL>>>(p_img, p_wqb + (size_t)p * INNER * K3_IMG,
                                             out, K3_IMG, p, 3 * TELEMS);
    for (int p = 0; p < 3; p++)
        hmma_gemm<<<grid, blk, SMEM_TOTAL>>>(p_txt, p_wkb + (size_t)p * INNER * K3_TXT,
                                             out, K3_TXT, 3 + p, 4 * TELEMS);
}

// round 4
// speedup vs baseline: 3.9370x; 1.5944x over previous
#include <cuda_runtime.h>
#include <cuda_fp16.h>
#include <cstdint>

// ---------------------------------------------------------------------------
// DynamicProjectionModule via fp16 mma.sync (arch-portable; tcgen05 rejected
// by the harness's compute_103 PTX pass).
//
// Accuracy: fp16 2-split.  A' = [Ahi|Alo] (A exactly), B' = fp16(B).
//   C = A * fp16(B); error ~2^-12 norm-relative (~1.4e-4) << 1e-3 gate.
// K' = 2K, B tile reused for both K-halves -> 146 GFLOP total (vs 219 for
// the bf16 3-split).
// All 9 logical GEMMs (Q,K,V + 3+3 routed banks) fused into ONE launch via a
// device-built tile-descriptor table.
// ---------------------------------------------------------------------------

#define BSZ      8
#define SEQ      1024
#define IMG_DIM  1024
#define TXT_DIM  768
#define INNER    1024
#define MROWS    (BSZ * SEQ)
#define TELEMS   ((long long)MROWS * INNER)

#define K2_IMG   (2 * IMG_DIM)   /* 2048 */
#define K2_TXT   (2 * TXT_DIM)   /* 1536 */

#define MAXTILES 324             /* 3*64 static + 2*66 routed worst case */

// ---- device scratch --------------------------------------------------------
__device__ int g_cnt[6];
__device__ int g_list[6][MROWS];

__device__ __half c_img[MROWS * K2_IMG];       // 32 MB
__device__ __half c_txt[MROWS * K2_TXT];       // 24 MB
__device__ __half c_wq [INNER * IMG_DIM];
__device__ __half c_wk [INNER * TXT_DIM];
__device__ __half c_wv [INNER * TXT_DIM];
__device__ __half c_wqb[3 * INNER * IMG_DIM];
__device__ __half c_wkb[3 * INNER * TXT_DIM];

struct Desc {
    const __half* A;      // split activations, width K2
    const __half* W;      // fp16 weights, width K2/2
    long long outBase;
    int K2;               // split K width (2048 or 1536)
    int slot;             // -1 plain, else g_list slot
    int rowBase;
};
__device__ Desc g_sched[MAXTILES];
__device__ int  g_ntiles;

// ---- helpers ---------------------------------------------------------------
__device__ __forceinline__ uint32_t smem_u32(const void* p) {
    uint32_t a;
    asm("{ .reg .u64 t; cvta.to.shared.u64 t, %1; cvt.u32.u64 %0, t; }" : "=r"(a) : "l"(p));
    return a;
}
__device__ __forceinline__ void cp16(uint32_t d, const void* g) {
    asm volatile("cp.async.cg.shared.global [%0], [%1], 16;" :: "r"(d), "l"(g));
}
__device__ __forceinline__ void cp_commit() { asm volatile("cp.async.commit_group;" ::: "memory"); }
template<int N> __device__ __forceinline__ void cp_wait() {
    asm volatile("cp.async.wait_group %0;" :: "n"(N) : "memory");
}
__device__ __forceinline__ void ldsm_x4(uint32_t& r0, uint32_t& r1, uint32_t& r2, uint32_t& r3,
                                        uint32_t addr) {
    asm volatile("ldmatrix.sync.aligned.m8n8.x4.shared.b16 {%0,%1,%2,%3}, [%4];"
                 : "=r"(r0), "=r"(r1), "=r"(r2), "=r"(r3) : "r"(addr));
}
__device__ __forceinline__ void mma16816(float* c, const uint32_t* a, const uint32_t* b) {
    asm volatile("mma.sync.aligned.m16n8k16.row.col.f32.f16.f16.f32 "
                 "{%0,%1,%2,%3}, {%4,%5,%6,%7}, {%8,%9}, {%0,%1,%2,%3};"
                 : "+f"(c[0]), "+f"(c[1]), "+f"(c[2]), "+f"(c[3])
                 : "r"(a[0]), "r"(a[1]), "r"(a[2]), "r"(a[3]), "r"(b[0]), "r"(b[1]));
}
#define SWZ(x) ((x) ^ (((x) >> 3) & 0x70))

// ---- setup -----------------------------------------------------------------
__global__ void init_kernel() {
    if (threadIdx.x < 6) g_cnt[threadIdx.x] = 0;
}

// fp64 accumulation: a flipped argmax corrupts a full 1024-wide output row.
__global__ void route_kernel(const float* __restrict__ img, const float* __restrict__ txt,
                             const float* __restrict__ Wrq, const float* __restrict__ Wrk) {
    int warp = (blockIdx.x * blockDim.x + threadIdx.x) >> 5;
    int lane = threadIdx.x & 31;
    int side = blockIdx.y;
    if (warp >= MROWS) return;
    const float* x;  const float* wr;  int dim;
    if (side == 0) { x = img + (size_t)warp * IMG_DIM; wr = Wrq; dim = IMG_DIM; }
    else           { x = txt + (size_t)warp * TXT_DIM; wr = Wrk; dim = TXT_DIM; }
    double s0 = 0, s1 = 0, s2 = 0;
    for (int k = lane; k < dim; k += 32) {
        double xv = (double)x[k];
        s0 += xv * (double)wr[k];
        s1 += xv * (double)wr[dim + k];
        s2 += xv * (double)wr[2 * dim + k];
    }
    #pragma unroll
    for (int off = 16; off; off >>= 1) {
        s0 += __shfl_down_sync(0xffffffffu, s0, off);
        s1 += __shfl_down_sync(0xffffffffu, s1, off);
        s2 += __shfl_down_sync(0xffffffffu, s2, off);
    }
    if (lane == 0) {
        int p = 0; double best = s0;
        if (s1 > best) { best = s1; p = 1; }
        if (s2 > best) { best = s2; p = 2; }
        int pos = atomicAdd(&g_cnt[side * 3 + p], 1);
        g_list[side * 3 + p][pos] = warp;
    }
}

// A-side: fp32 -> fp16 hi/lo split, layout [hi(K) | lo(K)] per row.
__global__ void convertA_kernel(const float* __restrict__ X, __half* __restrict__ Y,
                                int K, int total) {
    for (int i = blockIdx.x * blockDim.x + threadIdx.x; i < total;
         i += gridDim.x * blockDim.x) {
        int r = i / K, k = i - r * K;
        float x = X[i];
        __half hi = __float2half_rn(x);
        __half lo = __float2half_rn(x - __half2float(hi));
        size_t base = (size_t)r * (2 * K) + k;
        Y[base] = hi;  Y[base + K] = lo;
    }
}
// B-side: plain fp32 -> fp16.
__global__ void convertB_kernel(const float* __restrict__ X, __half* __restrict__ Y,
                                int total) {
    for (int i = blockIdx.x * blockDim.x + threadIdx.x; i < total;
         i += gridDim.x * blockDim.x)
        Y[i] = __float2half_rn(X[i]);
}

// Build the fused tile schedule (after routing).
__global__ void build_sched() {
    if (threadIdx.x != 0 || blockIdx.x != 0) return;
    int n = 0;
    for (int t = 0; t < 64; t++)
        g_sched[n++] = { c_img, c_wq, 0LL,           K2_IMG, -1, t * 128 };
    for (int t = 0; t < 64; t++)
        g_sched[n++] = { c_txt, c_wk, TELEMS,        K2_TXT, -1, t * 128 };
    for (int t = 0; t < 64; t++)
        g_sched[n++] = { c_txt, c_wv, 2 * TELEMS,    K2_TXT, -1, t * 128 };
    for (int p = 0; p < 3; p++) {
        int cnt = g_cnt[p];
        for (int t = 0; t * 128 < cnt; t++)
            g_sched[n++] = { c_img, c_wqb + (size_t)p * INNER * IMG_DIM,
                             3 * TELEMS, K2_IMG, p, t * 128 };
    }
    for (int p = 0; p < 3; p++) {
        int cnt = g_cnt[3 + p];
        for (int t = 0; t * 128 < cnt; t++)
            g_sched[n++] = { c_txt, c_wkb + (size_t)p * INNER * TXT_DIM,
                             4 * TELEMS, K2_TXT, 3 + p, t * 128 };
    }
    g_ntiles = n;
}

// ---- fused HMMA GEMM -------------------------------------------------------
// CTA tile 128(M) x 128(N), K-chunk 64, 3-stage cp.async pipeline, SW128
// swizzle. 8 warps 4(M) x 2(N), warp tile 32x64. B chunks wrap mod K2/2
// (the [hi|lo] K-halves share the same fp16 B).
#define KC        64
#define STAGES    3
#define AB_BYTES  (128 * 128)
#define STG_BYTES (2 * AB_BYTES)
#define CTRL_OFF  (STAGES * STG_BYTES)    /* 96 KB */
#define SMEM_TOTAL (CTRL_OFF + 512)

__global__ void __launch_bounds__(256, 2)
hmma_gemm(float* __restrict__ out)
{
    extern __shared__ char smem[];
    if ((int)blockIdx.x >= g_ntiles) return;
    const Desc d = g_sched[blockIdx.x];
    const __half* A = d.A;
    const __half* W = d.W;
    const int K2 = d.K2;
    const int KB = K2 >> 1;
    const int NCHUNK = K2 / KC;
    const int NB = NCHUNK >> 1;
    const int rowBase = d.rowBase;
    const int colBase = blockIdx.y * 128;
    const int cnt = (d.slot >= 0) ? g_cnt[d.slot] : MROWS;

    const int tid  = threadIdx.x;
    const int wid  = tid >> 5;
    const int lane = tid & 31;

    const uint32_t sb = smem_u32(smem);
    int* s_rowmap = (int*)(smem + CTRL_OFF);
    if (tid < 128) {
        int gr = rowBase + tid;
        s_rowmap[tid] = (d.slot < 0) ? gr : ((gr < cnt) ? g_list[d.slot][gr] : 0);
    }
    __syncthreads();

    const int wm = (wid >> 1) * 32;
    const int wn = (wid & 1) * 64;

    auto load_stage = [&](int buf, int chunk) {
        const int kcA = chunk * KC;
        const int kcB = (chunk >= NB ? chunk - NB : chunk) * KC;
        const uint32_t aB = sb + buf * STG_BYTES;
        #pragma unroll
        for (int j = 0; j < 8; j++) {
            int t = tid + j * 256;
            int r = t >> 3, c = t & 7;
            if (j < 4) {
                const __half* g = A + (size_t)s_rowmap[r] * K2 + kcA + c * 8;
                cp16(aB + SWZ(r * 128 + c * 16), g);
            } else {
                int rb = r - 128;
                const __half* g = W + (size_t)(colBase + rb) * KB + kcB + c * 8;
                cp16(aB + AB_BYTES + SWZ(rb * 128 + c * 16), g);
            }
        }
    };

    float acc[2][8][4];
    #pragma unroll
    for (int m = 0; m < 2; m++)
        #pragma unroll
        for (int n = 0; n < 8; n++)
            #pragma unroll
            for (int q = 0; q < 4; q++) acc[m][n][q] = 0.f;

    load_stage(0, 0); cp_commit();
    load_stage(1, 1); cp_commit();

    for (int c = 0; c < NCHUNK; c++) {
        const int buf = c % STAGES;
        cp_wait<STAGES - 2>();
        __syncthreads();

        if (c + 2 < NCHUNK) load_stage((c + 2) % STAGES, c + 2);
        cp_commit();

        const uint32_t aB = sb + buf * STG_BYTES;
        const uint32_t bB = aB + AB_BYTES;

        #pragma unroll
        for (int ks = 0; ks < 4; ks++) {
            uint32_t a[2][4];
            #pragma unroll
            for (int m = 0; m < 2; m++) {
                int row = wm + m * 16 + (lane & 15);
                int c16 = ks * 2 + (lane >> 4);
                ldsm_x4(a[m][0], a[m][1], a[m][2], a[m][3],
                        aB + SWZ(row * 128 + c16 * 16));
            }
            uint32_t b[8][2];
            #pragma unroll
            for (int t = 0; t < 4; t++) {
                int nrow = wn + t * 16 + (lane & 7) + ((lane >> 4) << 3);
                int c16  = ks * 2 + ((lane >> 3) & 1);
                uint32_t r0, r1, r2, r3;
                ldsm_x4(r0, r1, r2, r3, bB + SWZ(nrow * 128 + c16 * 16));
                b[2 * t][0] = r0;     b[2 * t][1] = r1;
                b[2 * t + 1][0] = r2; b[2 * t + 1][1] = r3;
            }
            #pragma unroll
            for (int m = 0; m < 2; m++)
                #pragma unroll
                for (int n = 0; n < 8; n++)
                    mma16816(acc[m][n], a[m], b[n]);
        }
        __syncthreads();
    }

    const int head = (colBase + wn) >> 6;
    #pragma unroll
    for (int m = 0; m < 2; m++) {
        #pragma unroll
        for (int half = 0; half < 2; half++) {
            int rr = wm + m * 16 + (lane >> 2) + half * 8;
            if (rowBase + rr >= cnt) continue;
            int mt = s_rowmap[rr];
            int bb = mt >> 10, sq = mt & 1023;
            long long off0 = d.outBase + (((long long)(bb * 16 + head) * 1024 + sq) * 64);
            #pragma unroll
            for (int n = 0; n < 8; n++) {
                int dd = n * 8 + 2 * (lane & 3);
                float2 v = make_float2(acc[m][n][half * 2], acc[m][n][half * 2 + 1]);
                *reinterpret_cast<float2*>(out + off0 + dd) = v;
            }
        }
    }
}

// ---- host ------------------------------------------------------------------
extern "C" void kernel_launch(void* const* d_in, const int* in_sizes, int n_in,
                              void* d_out, int out_size) {
    (void)in_sizes; (void)n_in; (void)out_size;
    const float* img = (const float*)d_in[0];
    const float* txt = (const float*)d_in[1];
    const float* Wq  = (const float*)d_in[2];
    const float* Wk  = (const float*)d_in[3];
    const float* Wv  = (const float*)d_in[4];
    const float* Wqb = (const float*)d_in[5];
    const float* Wkb = (const float*)d_in[6];
    const float* Wrq = (const float*)d_in[7];
    const float* Wrk = (const float*)d_in[8];
    float* out = (float*)d_out;

    cudaFuncSetAttribute(hmma_gemm, cudaFuncAttributeMaxDynamicSharedMemorySize,
                         SMEM_TOTAL);

    init_kernel<<<1, 32>>>();
    route_kernel<<<dim3(1024, 2), 256>>>(img, txt, Wrq, Wrk);

    __half *p_img, *p_txt, *p_wq, *p_wk, *p_wv, *p_wqb, *p_wkb;
    cudaGetSymbolAddress((void**)&p_img, c_img);
    cudaGetSymbolAddress((void**)&p_txt, c_txt);
    cudaGetSymbolAddress((void**)&p_wq,  c_wq);
    cudaGetSymbolAddress((void**)&p_wk,  c_wk);
    cudaGetSymbolAddress((void**)&p_wv,  c_wv);
    cudaGetSymbolAddress((void**)&p_wqb, c_wqb);
    cudaGetSymbolAddress((void**)&p_wkb, c_wkb);

    const int CB = 2368;
    convertA_kernel<<<CB, 256>>>(img, p_img, IMG_DIM, MROWS * IMG_DIM);
    convertA_kernel<<<CB, 256>>>(txt, p_txt, TXT_DIM, MROWS * TXT_DIM);
    convertB_kernel<<<CB, 256>>>(Wq,  p_wq,  INNER * IMG_DIM);
    convertB_kernel<<<CB, 256>>>(Wk,  p_wk,  INNER * TXT_DIM);
    convertB_kernel<<<CB, 256>>>(Wv,  p_wv,  INNER * TXT_DIM);
    convertB_kernel<<<CB, 256>>>(Wqb, p_wqb, 3 * INNER * IMG_DIM);
    convertB_kernel<<<CB, 256>>>(Wkb, p_wkb, 3 * INNER * TXT_DIM);

    build_sched<<<1, 32>>>();

    hmma_gemm<<<dim3(MAXTILES, 8), 256, SMEM_TOTAL>>>(out);
}

// round 6
// speedup vs baseline: 5.8794x; 1.4934x over previous
#include <cuda_runtime.h>
#include <cuda_fp16.h>
#include <cstdint>

// ---------------------------------------------------------------------------
// DynamicProjectionModule via pure-fp16 mma.sync (arch-portable; tcgen05 is
// rejected by the harness's plain compute_103 PTX pass).
//
// Accuracy: A and B both rounded to fp16, fp32 accumulation.
//   Measured err with exact A was 2.0e-4; A-rounding adds an independent
//   equal-size term -> ~2.8e-4 total, 3.5x under the 1e-3 gate.
// Routed projections (STE forward == argmax one-hot) are grouped GEMMs over
// per-bank compacted token lists; all 9 logical GEMMs fused into ONE launch
// via a device-built tile-descriptor table. Router uses fp64 accumulation
// (fp32 would flip ~3 argmaxes -> 1e-2 rel err).
// ---------------------------------------------------------------------------

#define BSZ      8
#define SEQ      1024
#define IMG_DIM  1024
#define TXT_DIM  768
#define INNER    1024
#define MROWS    (BSZ * SEQ)
#define TELEMS   ((long long)MROWS * INNER)

#define MAXTILES 324

// ---- device scratch --------------------------------------------------------
__device__ int g_cnt[6];
__device__ int g_list[6][MROWS];

__device__ __half c_img[MROWS * IMG_DIM];      // 16 MB
__device__ __half c_txt[MROWS * TXT_DIM];      // 12 MB
__device__ __half c_wq [INNER * IMG_DIM];
__device__ __half c_wk [INNER * TXT_DIM];
__device__ __half c_wv [INNER * TXT_DIM];
__device__ __half c_wqb[3 * INNER * IMG_DIM];
__device__ __half c_wkb[3 * INNER * TXT_DIM];

struct Desc {
    const __half* A;      // fp16 activations, width K
    const __half* W;      // fp16 weights, width K
    long long outBase;
    int K;
    int slot;             // -1 plain, else g_list slot
    int rowBase;
};
__device__ Desc g_sched[MAXTILES];
__device__ int  g_ntiles;

// ---- helpers ---------------------------------------------------------------
__device__ __forceinline__ uint32_t smem_u32(const void* p) {
    uint32_t a;
    asm("{ .reg .u64 t; cvta.to.shared.u64 t, %1; cvt.u32.u64 %0, t; }" : "=r"(a) : "l"(p));
    return a;
}
__device__ __forceinline__ void cp16(uint32_t d, const void* g) {
    asm volatile("cp.async.cg.shared.global [%0], [%1], 16;" :: "r"(d), "l"(g));
}
__device__ __forceinline__ void cp_commit() { asm volatile("cp.async.commit_group;" ::: "memory"); }
template<int N> __device__ __forceinline__ void cp_wait() {
    asm volatile("cp.async.wait_group %0;" :: "n"(N) : "memory");
}
__device__ __forceinline__ void ldsm_x4(uint32_t& r0, uint32_t& r1, uint32_t& r2, uint32_t& r3,
                                        uint32_t addr) {
    asm volatile("ldmatrix.sync.aligned.m8n8.x4.shared.b16 {%0,%1,%2,%3}, [%4];"
                 : "=r"(r0), "=r"(r1), "=r"(r2), "=r"(r3) : "r"(addr));
}
__device__ __forceinline__ void mma16816(float* c, const uint32_t* a, const uint32_t* b) {
    asm volatile("mma.sync.aligned.m16n8k16.row.col.f32.f16.f16.f32 "
                 "{%0,%1,%2,%3}, {%4,%5,%6,%7}, {%8,%9}, {%0,%1,%2,%3};"
                 : "+f"(c[0]), "+f"(c[1]), "+f"(c[2]), "+f"(c[3])
                 : "r"(a[0]), "r"(a[1]), "r"(a[2]), "r"(a[3]), "r"(b[0]), "r"(b[1]));
}
#define SWZ(x) ((x) ^ (((x) >> 3) & 0x70))

// ---- setup -----------------------------------------------------------------
__global__ void init_kernel() {
    if (threadIdx.x < 6) g_cnt[threadIdx.x] = 0;
}

__global__ void route_kernel(const float* __restrict__ img, const float* __restrict__ txt,
                             const float* __restrict__ Wrq, const float* __restrict__ Wrk) {
    int warp = (blockIdx.x * blockDim.x + threadIdx.x) >> 5;
    int lane = threadIdx.x & 31;
    int side = blockIdx.y;
    if (warp >= MROWS) return;
    const float* x;  const float* wr;  int dim;
    if (side == 0) { x = img + (size_t)warp * IMG_DIM; wr = Wrq; dim = IMG_DIM; }
    else           { x = txt + (size_t)warp * TXT_DIM; wr = Wrk; dim = TXT_DIM; }
    double s0 = 0, s1 = 0, s2 = 0;
    for (int k = lane; k < dim; k += 32) {
        double xv = (double)x[k];
        s0 += xv * (double)wr[k];
        s1 += xv * (double)wr[dim + k];
        s2 += xv * (double)wr[2 * dim + k];
    }
    #pragma unroll
    for (int off = 16; off; off >>= 1) {
        s0 += __shfl_down_sync(0xffffffffu, s0, off);
        s1 += __shfl_down_sync(0xffffffffu, s1, off);
        s2 += __shfl_down_sync(0xffffffffu, s2, off);
    }
    if (lane == 0) {
        int p = 0; double best = s0;
        if (s1 > best) { best = s1; p = 1; }
        if (s2 > best) { best = s2; p = 2; }
        int pos = atomicAdd(&g_cnt[side * 3 + p], 1);
        g_list[side * 3 + p][pos] = warp;
    }
}

// Vectorized fp32 -> fp16 cast: 8 elements/thread (2x float4 in, 1x uint4 out).
__global__ void convert_kernel(const float* __restrict__ X, __half* __restrict__ Y,
                               int total8) {
    size_t stride = (size_t)gridDim.x * blockDim.x;
    for (size_t i = (size_t)blockIdx.x * blockDim.x + threadIdx.x; i < (size_t)total8;
         i += stride) {
        const float4* p = reinterpret_cast<const float4*>(X) + 2 * i;
        float4 a = p[0], b = p[1];
        __half2 h0 = __floats2half2_rn(a.x, a.y);
        __half2 h1 = __floats2half2_rn(a.z, a.w);
        __half2 h2 = __floats2half2_rn(b.x, b.y);
        __half2 h3 = __floats2half2_rn(b.z, b.w);
        uint4 o;
        o.x = *reinterpret_cast<uint32_t*>(&h0);
        o.y = *reinterpret_cast<uint32_t*>(&h1);
        o.z = *reinterpret_cast<uint32_t*>(&h2);
        o.w = *reinterpret_cast<uint32_t*>(&h3);
        reinterpret_cast<uint4*>(Y)[i] = o;
    }
}

__global__ void build_sched() {
    if (threadIdx.x != 0 || blockIdx.x != 0) return;
    int n = 0;
    for (int t = 0; t < 64; t++)
        g_sched[n++] = { c_img, c_wq, 0LL,        IMG_DIM, -1, t * 128 };
    for (int t = 0; t < 64; t++)
        g_sched[n++] = { c_txt, c_wk, TELEMS,     TXT_DIM, -1, t * 128 };
    for (int t = 0; t < 64; t++)
        g_sched[n++] = { c_txt, c_wv, 2 * TELEMS, TXT_DIM, -1, t * 128 };
    for (int p = 0; p < 3; p++) {
        int cnt = g_cnt[p];
        for (int t = 0; t * 128 < cnt; t++)
            g_sched[n++] = { c_img, c_wqb + (size_t)p * INNER * IMG_DIM,
                             3 * TELEMS, IMG_DIM, p, t * 128 };
    }
    for (int p = 0; p < 3; p++) {
        int cnt = g_cnt[3 + p];
        for (int t = 0; t * 128 < cnt; t++)
            g_sched[n++] = { c_txt, c_wkb + (size_t)p * INNER * TXT_DIM,
                             4 * TELEMS, TXT_DIM, 3 + p, t * 128 };
    }
    g_ntiles = n;
}

// ---- fused HMMA GEMM -------------------------------------------------------
// CTA tile 128x128, K-chunk 64, 3-stage cp.async pipeline, SW128 swizzle.
// 8 warps 4(M) x 2(N), warp tile 32x64.
#define KC        64
#define STAGES    3
#define AB_BYTES  (128 * 128)
#define STG_BYTES (2 * AB_BYTES)
#define CTRL_OFF  (STAGES * STG_BYTES)    /* 96 KB */
#define SMEM_TOTAL (CTRL_OFF + 512)

__global__ void __launch_bounds__(256, 2)
hmma_gemm(float* __restrict__ out)
{
    extern __shared__ char smem[];
    if ((int)blockIdx.x >= g_ntiles) return;
    const Desc d = g_sched[blockIdx.x];
    const __half* A = d.A;
    const __half* W = d.W;
    const int K = d.K;
    const int NCHUNK = K / KC;
    const int rowBase = d.rowBase;
    const int colBase = blockIdx.y * 128;
    const int cnt = (d.slot >= 0) ? g_cnt[d.slot] : MROWS;

    const int tid  = threadIdx.x;
    const int wid  = tid >> 5;
    const int lane = tid & 31;

    const uint32_t sb = smem_u32(smem);
    int* s_rowmap = (int*)(smem + CTRL_OFF);
    if (tid < 128) {
        int gr = rowBase + tid;
        s_rowmap[tid] = (d.slot < 0) ? gr : ((gr < cnt) ? g_list[d.slot][gr] : 0);
    }
    __syncthreads();

    const int wm = (wid >> 1) * 32;
    const int wn = (wid & 1) * 64;

    auto load_stage = [&](int buf, int chunk) {
        const int kc = chunk * KC;
        const uint32_t aB = sb + buf * STG_BYTES;
        #pragma unroll
        for (int j = 0; j < 8; j++) {
            int t = tid + j * 256;
            int r = t >> 3, c = t & 7;
            if (j < 4) {
                const __half* g = A + (size_t)s_rowmap[r] * K + kc + c * 8;
                cp16(aB + SWZ(r * 128 + c * 16), g);
            } else {
                int rb = r - 128;
                const __half* g = W + (size_t)(colBase + rb) * K + kc + c * 8;
                cp16(aB + AB_BYTES + SWZ(rb * 128 + c * 16), g);
            }
        }
    };

    float acc[2][8][4];
    #pragma unroll
    for (int m = 0; m < 2; m++)
        #pragma unroll
        for (int n = 0; n < 8; n++)
            #pragma unroll
            for (int q = 0; q < 4; q++) acc[m][n][q] = 0.f;

    load_stage(0, 0); cp_commit();
    load_stage(1, 1); cp_commit();

    for (int c = 0; c < NCHUNK; c++) {
        const int buf = c % STAGES;
        cp_wait<STAGES - 2>();
        __syncthreads();

        if (c + 2 < NCHUNK) load_stage((c + 2) % STAGES, c + 2);
        cp_commit();

        const uint32_t aB = sb + buf * STG_BYTES;
        const uint32_t bB = aB + AB_BYTES;

        #pragma unroll
        for (int ks = 0; ks < 4; ks++) {
            uint32_t a[2][4];
            #pragma unroll
            for (int m = 0; m < 2; m++) {
                int row = wm + m * 16 + (lane & 15);
                int c16 = ks * 2 + (lane >> 4);
                ldsm_x4(a[m][0], a[m][1], a[m][2], a[m][3],
                        aB + SWZ(row * 128 + c16 * 16));
            }
            uint32_t b[8][2];
            #pragma unroll
            for (int t = 0; t < 4; t++) {
                int nrow = wn + t * 16 + (lane & 7) + ((lane >> 4) << 3);
                int c16  = ks * 2 + ((lane >> 3) & 1);
                uint32_t r0, r1, r2, r3;
                ldsm_x4(r0, r1, r2, r3, bB + SWZ(nrow * 128 + c16 * 16));
                b[2 * t][0] = r0;     b[2 * t][1] = r1;
                b[2 * t + 1][0] = r2; b[2 * t + 1][1] = r3;
            }
            #pragma unroll
            for (int m = 0; m < 2; m++)
                #pragma unroll
                for (int n = 0; n < 8; n++)
                    mma16816(acc[m][n], a[m], b[n]);
        }
        __syncthreads();
    }

    const int head = (colBase + wn) >> 6;
    #pragma unroll
    for (int m = 0; m < 2; m++) {
        #pragma unroll
        for (int half = 0; half < 2; half++) {
            int rr = wm + m * 16 + (lane >> 2) + half * 8;
            if (rowBase + rr >= cnt) continue;
            int mt = s_rowmap[rr];
            int bb = mt >> 10, sq = mt & 1023;
            long long off0 = d.outBase + (((long long)(bb * 16 + head) * 1024 + sq) * 64);
            #pragma unroll
            for (int n = 0; n < 8; n++) {
                int dd = n * 8 + 2 * (lane & 3);
                float2 v = make_float2(acc[m][n][half * 2], acc[m][n][half * 2 + 1]);
                *reinterpret_cast<float2*>(out + off0 + dd) = v;
            }
        }
    }
}

// ---- host ------------------------------------------------------------------
extern "C" void kernel_launch(void* const* d_in, const int* in_sizes, int n_in,
                              void* d_out, int out_size) {
    (void)in_sizes; (void)n_in; (void)out_size;
    const float* img = (const float*)d_in[0];
    const float* txt = (const float*)d_in[1];
    const float* Wq  = (const float*)d_in[2];
    const float* Wk  = (const float*)d_in[3];
    const float* Wv  = (const float*)d_in[4];
    const float* Wqb = (const float*)d_in[5];
    const float* Wkb = (const float*)d_in[6];
    const float* Wrq = (const float*)d_in[7];
    const float* Wrk = (const float*)d_in[8];
    float* out = (float*)d_out;

    cudaFuncSetAttribute(hmma_gemm, cudaFuncAttributeMaxDynamicSharedMemorySize,
                         SMEM_TOTAL);

    init_kernel<<<1, 32>>>();
    route_kernel<<<dim3(1024, 2), 256>>>(img, txt, Wrq, Wrk);

    __half *p_img, *p_txt, *p_wq, *p_wk, *p_wv, *p_wqb, *p_wkb;
    cudaGetSymbolAddress((void**)&p_img, c_img);
    cudaGetSymbolAddress((void**)&p_txt, c_txt);
    cudaGetSymbolAddress((void**)&p_wq,  c_wq);
    cudaGetSymbolAddress((void**)&p_wk,  c_wk);
    cudaGetSymbolAddress((void**)&p_wv,  c_wv);
    cudaGetSymbolAddress((void**)&p_wqb, c_wqb);
    cudaGetSymbolAddress((void**)&p_wkb, c_wkb);

    const int CB = 1184;
    convert_kernel<<<CB, 256>>>(img, p_img, MROWS * IMG_DIM / 8);
    convert_kernel<<<CB, 256>>>(txt, p_txt, MROWS * TXT_DIM / 8);
    convert_kernel<<<CB, 256>>>(Wq,  p_wq,  INNER * IMG_DIM / 8);
    convert_kernel<<<CB, 256>>>(Wk,  p_wk,  INNER * TXT_DIM / 8);
    convert_kernel<<<CB, 256>>>(Wv,  p_wv,  INNER * TXT_DIM / 8);
    convert_kernel<<<CB, 256>>>(Wqb, p_wqb, 3 * INNER * IMG_DIM / 8);
    convert_kernel<<<CB, 256>>>(Wkb, p_wkb, 3 * INNER * TXT_DIM / 8);

    build_sched<<<1, 32>>>();

    hmma_gemm<<<dim3(MAXTILES, 8), 256, SMEM_TOTAL>>>(out);
}

// round 7
// speedup vs baseline: 5.9215x; 1.0072x over previous
#include <cuda_runtime.h>
#include <cuda_fp16.h>
#include <cstdint>

// ---------------------------------------------------------------------------
// DynamicProjectionModule via pure-fp16 mma.sync (arch-portable; tcgen05 is
// rejected by the harness's plain compute_103 PTX pass).
//
// Accuracy: A and B rounded to fp16, fp32 accumulation -> rel_err ~2.9e-4
// (measured), 3.4x under the 1e-3 gate. Router uses fp64 accumulation so the
// STE argmax matches jax's fp32 scores.
// All 9 logical GEMMs (Q,K,V + 3+3 routed banks) fused into ONE launch with
// CTA tile 128x256, warp tile 64x64 (8 warps, 2x4), 3-stage cp.async.
// ---------------------------------------------------------------------------

#define BSZ      8
#define SEQ      1024
#define IMG_DIM  1024
#define TXT_DIM  768
#define INNER    1024
#define MROWS    (BSZ * SEQ)
#define TELEMS   ((long long)MROWS * INNER)

#define MAXTILES 324

// ---- device scratch --------------------------------------------------------
__device__ int g_cnt[6];
__device__ int g_list[6][MROWS];

__device__ __half c_img[MROWS * IMG_DIM];
__device__ __half c_txt[MROWS * TXT_DIM];
__device__ __half c_wq [INNER * IMG_DIM];
__device__ __half c_wk [INNER * TXT_DIM];
__device__ __half c_wv [INNER * TXT_DIM];
__device__ __half c_wqb[3 * INNER * IMG_DIM];
__device__ __half c_wkb[3 * INNER * TXT_DIM];

struct Desc {
    const __half* A;
    const __half* W;
    long long outBase;
    int K;
    int slot;             // -1 plain, else g_list slot
    int rowBase;
};
__device__ Desc g_sched[MAXTILES];
__device__ int  g_ntiles;

// ---- helpers ---------------------------------------------------------------
__device__ __forceinline__ uint32_t smem_u32(const void* p) {
    uint32_t a;
    asm("{ .reg .u64 t; cvta.to.shared.u64 t, %1; cvt.u32.u64 %0, t; }" : "=r"(a) : "l"(p));
    return a;
}
__device__ __forceinline__ void cp16(uint32_t d, const void* g) {
    asm volatile("cp.async.cg.shared.global [%0], [%1], 16;" :: "r"(d), "l"(g));
}
__device__ __forceinline__ void cp_commit() { asm volatile("cp.async.commit_group;" ::: "memory"); }
template<int N> __device__ __forceinline__ void cp_wait() {
    asm volatile("cp.async.wait_group %0;" :: "n"(N) : "memory");
}
__device__ __forceinline__ void ldsm_x4(uint32_t& r0, uint32_t& r1, uint32_t& r2, uint32_t& r3,
                                        uint32_t addr) {
    asm volatile("ldmatrix.sync.aligned.m8n8.x4.shared.b16 {%0,%1,%2,%3}, [%4];"
                 : "=r"(r0), "=r"(r1), "=r"(r2), "=r"(r3) : "r"(addr));
}
__device__ __forceinline__ void mma16816(float* c, const uint32_t* a, const uint32_t* b) {
    asm volatile("mma.sync.aligned.m16n8k16.row.col.f32.f16.f16.f32 "
                 "{%0,%1,%2,%3}, {%4,%5,%6,%7}, {%8,%9}, {%0,%1,%2,%3};"
                 : "+f"(c[0]), "+f"(c[1]), "+f"(c[2]), "+f"(c[3])
                 : "r"(a[0]), "r"(a[1]), "r"(a[2]), "r"(a[3]), "r"(b[0]), "r"(b[1]));
}
#define SWZ(x) ((x) ^ (((x) >> 3) & 0x70))

// ---- setup -----------------------------------------------------------------
__global__ void init_kernel() {
    if (threadIdx.x < 6) g_cnt[threadIdx.x] = 0;
}

__global__ void route_kernel(const float* __restrict__ img, const float* __restrict__ txt,
                             const float* __restrict__ Wrq, const float* __restrict__ Wrk) {
    int warp = (blockIdx.x * blockDim.x + threadIdx.x) >> 5;
    int lane = threadIdx.x & 31;
    int side = blockIdx.y;
    if (warp >= MROWS) return;
    const float* x;  const float* wr;  int dim;
    if (side == 0) { x = img + (size_t)warp * IMG_DIM; wr = Wrq; dim = IMG_DIM; }
    else           { x = txt + (size_t)warp * TXT_DIM; wr = Wrk; dim = TXT_DIM; }
    double s0 = 0, s1 = 0, s2 = 0;
    for (int k = lane; k < dim; k += 32) {
        double xv = (double)x[k];
        s0 += xv * (double)wr[k];
        s1 += xv * (double)wr[dim + k];
        s2 += xv * (double)wr[2 * dim + k];
    }
    #pragma unroll
    for (int off = 16; off; off >>= 1) {
        s0 += __shfl_down_sync(0xffffffffu, s0, off);
        s1 += __shfl_down_sync(0xffffffffu, s1, off);
        s2 += __shfl_down_sync(0xffffffffu, s2, off);
    }
    if (lane == 0) {
        int p = 0; double best = s0;
        if (s1 > best) { best = s1; p = 1; }
        if (s2 > best) { best = s2; p = 2; }
        int pos = atomicAdd(&g_cnt[side * 3 + p], 1);
        g_list[side * 3 + p][pos] = warp;
    }
}

// Fused fp32 -> fp16 cast over all 7 tensors, 8 elem per unit of work.
struct ConvArgs {
    const float* src[7];
    __half*      dst[7];
    int          end[7];   // cumulative end, in 8-element units
};
__global__ void convert_all(ConvArgs a) {
    const int total = a.end[6];
    const int stride = gridDim.x * blockDim.x;
    for (int i = blockIdx.x * blockDim.x + threadIdx.x; i < total; i += stride) {
        int s = 0;
        #pragma unroll
        for (int t = 0; t < 6; t++) s += (i >= a.end[t]);
        int j = i - (s ? a.end[s - 1] : 0);
        const float4* p = reinterpret_cast<const float4*>(a.src[s]) + 2 * (size_t)j;
        float4 x = p[0], y = p[1];
        __half2 h0 = __floats2half2_rn(x.x, x.y);
        __half2 h1 = __floats2half2_rn(x.z, x.w);
        __half2 h2 = __floats2half2_rn(y.x, y.y);
        __half2 h3 = __floats2half2_rn(y.z, y.w);
        uint4 o;
        o.x = *reinterpret_cast<uint32_t*>(&h0);
        o.y = *reinterpret_cast<uint32_t*>(&h1);
        o.z = *reinterpret_cast<uint32_t*>(&h2);
        o.w = *reinterpret_cast<uint32_t*>(&h3);
        reinterpret_cast<uint4*>(a.dst[s])[j] = o;
    }
}

__global__ void build_sched() {
    if (threadIdx.x != 0 || blockIdx.x != 0) return;
    int n = 0;
    for (int t = 0; t < 64; t++)
        g_sched[n++] = { c_img, c_wq, 0LL,        IMG_DIM, -1, t * 128 };
    for (int t = 0; t < 64; t++)
        g_sched[n++] = { c_txt, c_wk, TELEMS,     TXT_DIM, -1, t * 128 };
    for (int t = 0; t < 64; t++)
        g_sched[n++] = { c_txt, c_wv, 2 * TELEMS, TXT_DIM, -1, t * 128 };
    for (int p = 0; p < 3; p++) {
        int cnt = g_cnt[p];
        for (int t = 0; t * 128 < cnt; t++)
            g_sched[n++] = { c_img, c_wqb + (size_t)p * INNER * IMG_DIM,
                             3 * TELEMS, IMG_DIM, p, t * 128 };
    }
    for (int p = 0; p < 3; p++) {
        int cnt = g_cnt[3 + p];
        for (int t = 0; t * 128 < cnt; t++)
            g_sched[n++] = { c_txt, c_wkb + (size_t)p * INNER * TXT_DIM,
                             4 * TELEMS, TXT_DIM, 3 + p, t * 128 };
    }
    g_ntiles = n;
}

// ---- fused HMMA GEMM -------------------------------------------------------
// CTA tile 128(M) x 256(N), K-chunk 64, 3-stage cp.async, SW128 swizzle.
// 8 warps as 2(M) x 4(N); warp tile 64x64 (4 m16 x 8 n8 frags, 32 MMA/k16).
#define KC        64
#define A_BYTES   (128 * 128)             /* 16 KB */
#define B_BYTES   (256 * 128)             /* 32 KB */
#define STG_BYTES (A_BYTES + B_BYTES)     /* 48 KB */
#define STAGES    3
#define CTRL_OFF  (STAGES * STG_BYTES)    /* 144 KB */
#define SMEM_TOTAL (CTRL_OFF + 512)

__global__ void __launch_bounds__(256, 1)
hmma_gemm(float* __restrict__ out)
{
    extern __shared__ char smem[];
    if ((int)blockIdx.x >= g_ntiles) return;
    const Desc d = g_sched[blockIdx.x];
    const __half* A = d.A;
    const __half* W = d.W;
    const int K = d.K;
    const int NCHUNK = K / KC;
    const int rowBase = d.rowBase;
    const int colBase = blockIdx.y * 256;
    const int cnt = (d.slot >= 0) ? g_cnt[d.slot] : MROWS;

    const int tid  = threadIdx.x;
    const int wid  = tid >> 5;
    const int lane = tid & 31;

    const uint32_t sb = smem_u32(smem);
    int* s_rowmap = (int*)(smem + CTRL_OFF);
    if (tid < 128) {
        int gr = rowBase + tid;
        s_rowmap[tid] = (d.slot < 0) ? gr : ((gr < cnt) ? g_list[d.slot][gr] : 0);
    }
    __syncthreads();

    const int wm = (wid & 1) * 64;     // warp M offset (0/64)
    const int wn = (wid >> 1) * 64;    // warp N offset (0/64/128/192)

    auto load_stage = [&](int buf, int chunk) {
        const int kc = chunk * KC;
        const uint32_t base = sb + buf * STG_BYTES;
        #pragma unroll
        for (int j = 0; j < 4; j++) {                  // A: 1024 x 16B
            int t = tid + j * 256;
            int r = t >> 3, c = t & 7;
            const __half* g = A + (size_t)s_rowmap[r] * K + kc + c * 8;
            cp16(base + SWZ(r * 128 + c * 16), g);
        }
        #pragma unroll
        for (int j = 0; j < 8; j++) {                  // B: 2048 x 16B
            int t = tid + j * 256;
            int r = t >> 3, c = t & 7;
            const __half* g = W + (size_t)(colBase + r) * K + kc + c * 8;
            cp16(base + A_BYTES + SWZ(r * 128 + c * 16), g);
        }
    };

    float acc[4][8][4];
    #pragma unroll
    for (int m = 0; m < 4; m++)
        #pragma unroll
        for (int n = 0; n < 8; n++)
            #pragma unroll
            for (int q = 0; q < 4; q++) acc[m][n][q] = 0.f;

    load_stage(0, 0); cp_commit();
    load_stage(1, 1); cp_commit();

    for (int c = 0; c < NCHUNK; c++) {
        const int buf = c % STAGES;
        cp_wait<STAGES - 2>();
        __syncthreads();

        if (c + 2 < NCHUNK) load_stage((c + 2) % STAGES, c + 2);
        cp_commit();

        const uint32_t aB = sb + buf * STG_BYTES;
        const uint32_t bB = aB + A_BYTES;

        #pragma unroll
        for (int ks = 0; ks < 4; ks++) {
            uint32_t a[4][4];
            #pragma unroll
            for (int m = 0; m < 4; m++) {
                int row = wm + m * 16 + (lane & 15);
                int c16 = ks * 2 + (lane >> 4);
                ldsm_x4(a[m][0], a[m][1], a[m][2], a[m][3],
                        aB + SWZ(row * 128 + c16 * 16));
            }
            uint32_t b[8][2];
            #pragma unroll
            for (int t = 0; t < 4; t++) {
                int nrow = wn + t * 16 + (lane & 7) + ((lane >> 4) << 3);
                int c16  = ks * 2 + ((lane >> 3) & 1);
                uint32_t r0, r1, r2, r3;
                ldsm_x4(r0, r1, r2, r3, bB + SWZ(nrow * 128 + c16 * 16));
                b[2 * t][0] = r0;     b[2 * t][1] = r1;
                b[2 * t + 1][0] = r2; b[2 * t + 1][1] = r3;
            }
            #pragma unroll
            for (int m = 0; m < 4; m++)
                #pragma unroll
                for (int n = 0; n < 8; n++)
                    mma16816(acc[m][n], a[m], b[n]);
        }
        __syncthreads();
    }

    // epilogue: warp covers rows [wm, wm+64), cols [wn, wn+64) = one head
    const int head = (colBase + wn) >> 6;
    #pragma unroll
    for (int m = 0; m < 4; m++) {
        #pragma unroll
        for (int half = 0; half < 2; half++) {
            int rr = wm + m * 16 + (lane >> 2) + half * 8;
            if (rowBase + rr >= cnt) continue;
            int mt = s_rowmap[rr];
            int bb = mt >> 10, sq = mt & 1023;
            long long off0 = d.outBase + (((long long)(bb * 16 + head) * 1024 + sq) * 64);
            #pragma unroll
            for (int n = 0; n < 8; n++) {
                int dd = n * 8 + 2 * (lane & 3);
                float2 v = make_float2(acc[m][n][half * 2], acc[m][n][half * 2 + 1]);
                *reinterpret_cast<float2*>(out + off0 + dd) = v;
            }
        }
    }
}

// ---- host ------------------------------------------------------------------
extern "C" void kernel_launch(void* const* d_in, const int* in_sizes, int n_in,
                              void* d_out, int out_size) {
    (void)in_sizes; (void)n_in; (void)out_size;
    const float* img = (const float*)d_in[0];
    const float* txt = (const float*)d_in[1];
    const float* Wq  = (const float*)d_in[2];
    const float* Wk  = (const float*)d_in[3];
    const float* Wv  = (const float*)d_in[4];
    const float* Wqb = (const float*)d_in[5];
    const float* Wkb = (const float*)d_in[6];
    const float* Wrq = (const float*)d_in[7];
    const float* Wrk = (const float*)d_in[8];
    float* out = (float*)d_out;

    cudaFuncSetAttribute(hmma_gemm, cudaFuncAttributeMaxDynamicSharedMemorySize,
                         SMEM_TOTAL);

    init_kernel<<<1, 32>>>();
    route_kernel<<<dim3(1024, 2), 256>>>(img, txt, Wrq, Wrk);

    __half *p_img, *p_txt, *p_wq, *p_wk, *p_wv, *p_wqb, *p_wkb;
    cudaGetSymbolAddress((void**)&p_img, c_img);
    cudaGetSymbolAddress((void**)&p_txt, c_txt);
    cudaGetSymbolAddress((void**)&p_wq,  c_wq);
    cudaGetSymbolAddress((void**)&p_wk,  c_wk);
    cudaGetSymbolAddress((void**)&p_wv,  c_wv);
    cudaGetSymbolAddress((void**)&p_wqb, c_wqb);
    cudaGetSymbolAddress((void**)&p_wkb, c_wkb);

    ConvArgs ca;
    const float* srcs[7] = { img, txt, Wq, Wk, Wv, Wqb, Wkb };
    __half* dsts[7] = { p_img, p_txt, p_wq, p_wk, p_wv, p_wqb, p_wkb };
    int lens[7] = { MROWS * IMG_DIM / 8, MROWS * TXT_DIM / 8,
                    INNER * IMG_DIM / 8, INNER * TXT_DIM / 8, INNER * TXT_DIM / 8,
                    3 * INNER * IMG_DIM / 8, 3 * INNER * TXT_DIM / 8 };
    int accum = 0;
    for (int i = 0; i < 7; i++) {
        ca.src[i] = srcs[i];
        ca.dst[i] = dsts[i];
        accum += lens[i];
        ca.end[i] = accum;
    }
    convert_all<<<2368, 256>>>(ca);

    build_sched<<<1, 32>>>();

    hmma_gemm<<<dim3(MAXTILES, 4), 256, SMEM_TOTAL>>>(out);
}